// round 15
// baseline (speedup 1.0000x reference)
#include <cuda_runtime.h>
#include <math.h>
#include <stdint.h>

#define BATCH 32
#define S 2048
#define BS (BATCH * S)
#define EPSLN 1e-5f
#define L2E 1.4426950408889634f   // log2(e)

#define QKV_KSPLIT 8
#define FC2_KSPLIT 16
#define NCHEB 40

// ---------------- scratch (no allocations allowed) ----------------
__device__ float g_qp[QKV_KSPLIT * BS];
__device__ float g_kp[QKV_KSPLIT * BS];
__device__ float g_vp[QKV_KSPLIT * BS];
__device__ float g_qc[BS];
__device__ float g_kc[BS];
__device__ float g_vc[BS];
__device__ float g_act[BS];
__device__ float g_fcp[FC2_KSPLIT * BS];
__device__ float g_F[BATCH * NCHEB];
__device__ float g_G[BATCH * NCHEB];
__device__ float g_S[BATCH * NCHEB];    // moments S_m = sum_i T_m(u_i)
__device__ float g_aF[BATCH * NCHEB];   // Chebyshev coefs of F
__device__ float g_Zb[BATCH];           // per-batch softmax denominator
__device__ float g_rqmn[64], g_rqmx[64], g_rkmn[64], g_rkmx[64];  // 1024-elem chunks

__device__ __forceinline__ float ex2f(float x) {
    float y;
    asm("ex2.approx.f32 %0, %1;" : "=f"(y) : "f"(x));
    return y;
}

__device__ __forceinline__ void cp_async16(unsigned dst, const void* src) {
    asm volatile("cp.async.cg.shared.global [%0], [%1], 16;" :: "r"(dst), "l"(src));
}

// split float2 (x = even-k, y = odd-k) into packed bf16x2 hi and lo planes.
__device__ __forceinline__ void bsplit(float2 v, uint32_t& hi, uint32_t& lo) {
    uint32_t h;
    asm("cvt.rn.bf16x2.f32 %0, %1, %2;" : "=r"(h) : "f"(v.y), "f"(v.x));
    float fx = __uint_as_float(h << 16);
    float fy = __uint_as_float(h & 0xffff0000u);
    float lx = v.x - fx, ly = v.y - fy;
    uint32_t l;
    asm("cvt.rn.bf16x2.f32 %0, %1, %2;" : "=r"(l) : "f"(ly), "f"(lx));
    hi = h; lo = l;
}

__device__ __forceinline__ void mma_bf16(float acc[4],
                                         uint32_t a0, uint32_t a1, uint32_t a2, uint32_t a3,
                                         uint32_t b0, uint32_t b1) {
    asm volatile("mma.sync.aligned.m16n8k16.row.col.f32.bf16.bf16.f32 "
                 "{%0,%1,%2,%3}, {%4,%5,%6,%7}, {%8,%9}, {%0,%1,%2,%3};"
                 : "+f"(acc[0]), "+f"(acc[1]), "+f"(acc[2]), "+f"(acc[3])
                 : "r"(a0), "r"(a1), "r"(a2), "r"(a3), "r"(b0), "r"(b1));
}

// ---------------- bf16 tensor-core GEMM (unchanged from R12) ----------------
#define WSTRIDE 40
#define WSTAGE (128 * WSTRIDE)

template <int NCHUNK>
__device__ __forceinline__ void gemm_bf16(const float* __restrict__ X,
                                          const float* __restrict__ W,
                                          float* __restrict__ out,
                                          int c0, int kb0)
{
    __shared__ __align__(16) float sW[2][WSTAGE];
    __shared__ uint32_t sXh[512], sXl[512];

    const int tid = threadIdx.x;
    const int lane = tid & 31, w = tid >> 5;

    float acc[4][4];
    #pragma unroll
    for (int g = 0; g < 4; g++)
        #pragma unroll
        for (int j = 0; j < 4; j++) acc[g][j] = 0.f;

    const unsigned swbase = (unsigned)__cvta_generic_to_shared(&sW[0][0]);

    const int wrow = tid >> 3, wq = tid & 7;

    const int sg   = tid >> 6;
    const int sln  = (tid >> 1) & 31;
    const int sbrg = tid & 1;
    const int sn   = sg * 8 + (sln >> 2);
    const int skk  = sbrg * 8 + 2 * (sln & 3);
    const float* xp = X + (size_t)sn * S + kb0 + skk;

    #pragma unroll
    for (int i = 0; i < 4; i++) {
        int r = wrow + i * 32;
        cp_async16(swbase + (unsigned)((r * WSTRIDE + wq * 4) * 4),
                   W + (size_t)(c0 + r) * S + kb0 + wq * 4);
    }
    asm volatile("cp.async.commit_group;");
    float2 xr0 = *(const float2*)(xp);
    float2 xr1 = *(const float2*)(xp + 16);

    for (int ch = 0; ch < NCHUNK; ch++) {
        asm volatile("cp.async.wait_group 0;");
        __syncthreads();

        if (ch + 1 < NCHUNK) {
            const int kb = kb0 + (ch + 1) * 32;
            const unsigned stoff = (unsigned)(((ch + 1) & 1) * WSTAGE * 4);
            #pragma unroll
            for (int i = 0; i < 4; i++) {
                int r = wrow + i * 32;
                cp_async16(swbase + stoff + (unsigned)((r * WSTRIDE + wq * 4) * 4),
                           W + (size_t)(c0 + r) * S + kb + wq * 4);
            }
            asm volatile("cp.async.commit_group;");
        }

        {
            uint32_t h0, l0, h1, l1;
            bsplit(xr0, h0, l0);
            bsplit(xr1, h1, l1);
            sXh[tid] = h0;       sXl[tid] = l0;
            sXh[tid + 256] = h1; sXl[tid + 256] = l1;
        }
        if (ch + 1 < NCHUNK) {
            xr0 = *(const float2*)(xp + (ch + 1) * 32);
            xr1 = *(const float2*)(xp + (ch + 1) * 32 + 16);
        }
        __syncthreads();

        const float* ws = sW[ch & 1];
        const int rb = w * 16 + (lane >> 2);
        const int kc = 2 * (lane & 3);

        #pragma unroll
        for (int s = 0; s < 2; s++) {
            float2 ra0 = *(const float2*)&ws[rb * WSTRIDE + s * 16 + kc];
            float2 ra2 = *(const float2*)&ws[rb * WSTRIDE + s * 16 + 8 + kc];
            float2 ra1 = *(const float2*)&ws[(rb + 8) * WSTRIDE + s * 16 + kc];
            float2 ra3 = *(const float2*)&ws[(rb + 8) * WSTRIDE + s * 16 + 8 + kc];
            uint32_t A0h, A0l, A1h, A1l, A2h, A2l, A3h, A3l;
            bsplit(ra0, A0h, A0l);
            bsplit(ra1, A1h, A1l);
            bsplit(ra2, A2h, A2l);
            bsplit(ra3, A3h, A3l);

            #pragma unroll
            for (int g = 0; g < 4; g++) {
                const int base = ((s * 4 + g) << 6) + (lane << 1);
                uint2 bh = *(const uint2*)&sXh[base];
                uint2 bl = *(const uint2*)&sXl[base];
                mma_bf16(acc[g], A0h, A1h, A2h, A3h, bh.x, bh.y);
                mma_bf16(acc[g], A0h, A1h, A2h, A3h, bl.x, bl.y);
                mma_bf16(acc[g], A0l, A1l, A2l, A3l, bh.x, bh.y);
            }
        }
    }

    const int c = c0 + w * 16 + (lane >> 2);
    #pragma unroll
    for (int g = 0; g < 4; g++) {
        const int b = g * 8 + 2 * (lane & 3);
        out[(size_t)b * S + c]           = acc[g][0];
        out[(size_t)(b + 1) * S + c]     = acc[g][1];
        out[(size_t)b * S + c + 8]       = acc[g][2];
        out[(size_t)(b + 1) * S + c + 8] = acc[g][3];
    }
}

// ---------------- kernel 1: fused QKV GEMM ----------------
__global__ void __launch_bounds__(256) qkv_kernel(const float* __restrict__ x,
                                                  const float* __restrict__ Wq,
                                                  const float* __restrict__ Wk,
                                                  const float* __restrict__ Wv) {
    const int z = blockIdx.z;
    const float* W = (z == 0) ? Wq : (z == 1 ? Wk : Wv);
    float* out = ((z == 0) ? g_qp : (z == 1 ? g_kp : g_vp)) + (size_t)blockIdx.y * BS;
    gemm_bf16<(S / QKV_KSPLIT) / 32>(x, W, out, blockIdx.x * 128,
                                     blockIdx.y * (S / QKV_KSPLIT));
}

// ---------------- kernel 1b: combine qkv partials (float4) + 1024-chunk min/max ------
// grid 64, block 256; each thread: 4 consecutive elems; block = one 1024-elem chunk.
__global__ void __launch_bounds__(256) combine_kernel() {
    __shared__ float r0[8], r1[8], r2[8], r3[8];
    const int tid = threadIdx.x;
    const int e0 = (blockIdx.x * 256 + tid) * 4;

    float4 q = make_float4(0.f, 0.f, 0.f, 0.f);
    float4 k = q, v = q;
    #pragma unroll
    for (int p = 0; p < QKV_KSPLIT; p++) {
        float4 a = *(const float4*)&g_qp[(size_t)p * BS + e0];
        float4 bq = *(const float4*)&g_kp[(size_t)p * BS + e0];
        float4 c = *(const float4*)&g_vp[(size_t)p * BS + e0];
        q.x += a.x; q.y += a.y; q.z += a.z; q.w += a.w;
        k.x += bq.x; k.y += bq.y; k.z += bq.z; k.w += bq.w;
        v.x += c.x; v.y += c.y; v.z += c.z; v.w += c.w;
    }
    *(float4*)&g_qc[e0] = q;
    *(float4*)&g_kc[e0] = k;
    *(float4*)&g_vc[e0] = v;

    float qmn = fminf(fminf(q.x, q.y), fminf(q.z, q.w));
    float qmx = fmaxf(fmaxf(q.x, q.y), fmaxf(q.z, q.w));
    float kmn = fminf(fminf(k.x, k.y), fminf(k.z, k.w));
    float kmx = fmaxf(fmaxf(k.x, k.y), fmaxf(k.z, k.w));
    #pragma unroll
    for (int off = 16; off > 0; off >>= 1) {
        qmn = fminf(qmn, __shfl_xor_sync(0xffffffffu, qmn, off));
        qmx = fmaxf(qmx, __shfl_xor_sync(0xffffffffu, qmx, off));
        kmn = fminf(kmn, __shfl_xor_sync(0xffffffffu, kmn, off));
        kmx = fmaxf(kmx, __shfl_xor_sync(0xffffffffu, kmx, off));
    }
    const int lane = tid & 31, wid = tid >> 5;
    if (lane == 0) { r0[wid] = qmn; r1[wid] = qmx; r2[wid] = kmn; r3[wid] = kmx; }
    __syncthreads();
    if (tid == 0) {
        float a = r0[0], b = r1[0], c = r2[0], d = r3[0];
        #pragma unroll
        for (int w = 1; w < 8; w++) {
            a = fminf(a, r0[w]); b = fmaxf(b, r1[w]);
            c = fminf(c, r2[w]); d = fmaxf(d, r3[w]);
        }
        g_rqmn[blockIdx.x] = a; g_rqmx[blockIdx.x] = b;
        g_rkmn[blockIdx.x] = c; g_rkmx[blockIdx.x] = d;
    }
}

// batch-level range + shift M (identical fp sequence wherever used; 2 chunks/batch)
__device__ __forceinline__ void batch_range(int b, float& c, float& h, float& M) {
    float qmn = fminf(g_rqmn[b * 2], g_rqmn[b * 2 + 1]);
    float qmx = fmaxf(g_rqmx[b * 2], g_rqmx[b * 2 + 1]);
    float kmn = fminf(g_rkmn[b * 2], g_rkmn[b * 2 + 1]);
    float kmx = fmaxf(g_rkmx[b * 2], g_rkmx[b * 2 + 1]);
    c = 0.5f * (qmn + qmx);
    h = fmaxf(0.5f * (qmx - qmn), 1e-30f);
    M = fmaxf(fmaxf(qmn * kmn, qmn * kmx), fmaxf(qmx * kmn, qmx * kmx));
}

// ---------------- kernel 2a: Chebyshev nodes (y<5) + q-moments (y==5) ----------------
__global__ void __launch_bounds__(256) cheb_nodes_kernel() {
    __shared__ float sk[S], sv[S];
    __shared__ float sprm[3];
    __shared__ float sS[NCHEB][9];

    const int b = blockIdx.x;
    const int tid = threadIdx.x;
    const int lane = tid & 31, w = tid >> 5;

    if (tid == 0) {
        float c, h, M;
        batch_range(b, c, h, M);
        sprm[0] = c; sprm[1] = h; sprm[2] = M;
    }

    if (blockIdx.y == 5) {
        // ---- moments path ----
        __syncthreads();
        const float c = sprm[0], hinv = 1.0f / sprm[1];

        float acc[NCHEB];
        #pragma unroll
        for (int m = 0; m < NCHEB; m++) acc[m] = 0.f;

        #pragma unroll
        for (int jj = 0; jj < 8; jj++) {
            const int i = tid + jj * 256;
            float u = fminf(1.f, fmaxf(-1.f, (g_qc[b * S + i] - c) * hinv));
            float t0 = 1.f, t1 = u;
            acc[0] += t0;
            acc[1] += t1;
            #pragma unroll
            for (int m = 2; m < NCHEB; m++) {
                float tm = fmaf(u + u, t1, -t0);
                acc[m] += tm;
                t0 = t1; t1 = tm;
            }
        }
        #pragma unroll
        for (int m = 0; m < NCHEB; m++) {
            float s = acc[m];
            #pragma unroll
            for (int off = 16; off > 0; off >>= 1)
                s += __shfl_xor_sync(0xffffffffu, s, off);
            if (lane == 0) sS[m][w] = s;
        }
        __syncthreads();
        if (tid < NCHEB) {
            float s = 0.f;
            #pragma unroll
            for (int ww = 0; ww < 8; ww++) s += sS[tid][ww];
            g_S[b * NCHEB + tid] = s;
        }
        return;
    }

    // ---- nodes path ----
    for (int idx = tid; idx < S; idx += 256) {
        sk[idx] = g_kc[b * S + idx];
        sv[idx] = g_vc[b * S + idx];
    }
    __syncthreads();
    const float c = sprm[0], h = sprm[1], Ml2e = sprm[2] * L2E;

    const int n = blockIdx.y * 8 + w;
    const float t = fmaf(h, cospif((n + 0.5f) * (1.0f / NCHEB)), c);
    const float tl = t * L2E;
    float F = 0.f, G = 0.f;
    #pragma unroll 4
    for (int j = lane; j < S; j += 32) {
        float e = ex2f(fmaf(tl, sk[j], -Ml2e));
        F = fmaf(e, sv[j], F);
        G += e;
    }
    #pragma unroll
    for (int off = 16; off > 0; off >>= 1) {
        F += __shfl_xor_sync(0xffffffffu, F, off);
        G += __shfl_xor_sync(0xffffffffu, G, off);
    }
    if (lane == 0) {
        g_F[b * NCHEB + n] = F;
        g_G[b * NCHEB + n] = G;
    }
}

// ---------------- kernel 2b: per-batch DCT coefficients + Z (ONCE) -------------------
// grid BATCH, block 256. Writes g_aF[b][m] and g_Zb[b].
__global__ void __launch_bounds__(256) cheb_coef_kernel() {
    __shared__ float scos[NCHEB][NCHEB + 1];
    __shared__ float sF[NCHEB], sG[NCHEB], sS[NCHEB], saG[NCHEB];
    __shared__ float zpart[NCHEB];

    const int b = blockIdx.x;
    const int tid = threadIdx.x;

    if (tid < NCHEB) {
        sF[tid] = g_F[b * NCHEB + tid];
        sG[tid] = g_G[b * NCHEB + tid];
        sS[tid] = g_S[b * NCHEB + tid];
    }
    for (int idx = tid; idx < NCHEB * NCHEB; idx += 256) {
        int m = idx / NCHEB, n = idx - m * NCHEB;
        scos[m][n] = cospif((float)(m * (2 * n + 1)) * (1.0f / (2 * NCHEB)));
    }
    __syncthreads();

    if (tid < 2 * NCHEB) {
        const int m = (tid < NCHEB) ? tid : (tid - NCHEB);
        const float* src = (tid < NCHEB) ? sF : sG;
        float s = 0.f;
        #pragma unroll 8
        for (int n = 0; n < NCHEB; n++)
            s = fmaf(src[n], scos[m][n], s);
        s *= (m == 0) ? (1.0f / NCHEB) : (2.0f / NCHEB);
        if (tid < NCHEB) g_aF[b * NCHEB + m] = s;
        else { saG[m] = s; zpart[m] = s * sS[m]; }
    }
    __syncthreads();
    if (tid == 0) {
        float z = 0.f;
        #pragma unroll 8
        for (int m = 0; m < NCHEB; m++) z += zpart[m];
        g_Zb[b] = z;
    }
}

// ---------------- kernel 2c: Clenshaw eval + activation -------------------------------
// grid (BATCH, 4), block 256, 2 i per thread (2 independent FMA chains).
__global__ void __launch_bounds__(256) cheb_evalact_kernel(const float* __restrict__ p2) {
    __shared__ float saF[NCHEB];
    __shared__ float sprm[2];
    __shared__ float sPs0, sPs1, sPs2;

    const int b = blockIdx.x;
    const int tid = threadIdx.x;

    if (tid == 0) {
        float c, h, M;
        batch_range(b, c, h, M);
        sprm[0] = c; sprm[1] = h;
    }
    if (tid == 32) {
        float p[5];
        #pragma unroll
        for (int t = 0; t < 5; t++) p[t] = p2[t];
        float pm = p[0];
        #pragma unroll
        for (int t = 1; t < 5; t++) pm = fmaxf(pm, p[t]);
        float pe[5], psum = 0.f;
        #pragma unroll
        for (int t = 0; t < 5; t++) { pe[t] = ex2f((p[t] - pm) * L2E); psum += pe[t]; }
        float inv = __fdividef(1.0f, psum);
        sPs0 = pe[0] * inv; sPs1 = pe[1] * inv; sPs2 = pe[2] * inv;
    }
    if (tid >= 64 && tid < 64 + NCHEB)
        saF[tid - 64] = g_aF[b * NCHEB + (tid - 64)];
    __syncthreads();

    const float c = sprm[0], hinv = 1.0f / sprm[1];
    const float Z = g_Zb[b];
    const float ps0 = sPs0, ps1 = sPs1, ps2 = sPs2;

    const int i0 = blockIdx.y * 512 + tid;
    float ua, ub;
    {
        float ta = g_qc[b * S + i0];
        float tb = g_qc[b * S + i0 + 256];
        ua = fminf(1.f, fmaxf(-1.f, (ta - c) * hinv));
        ub = fminf(1.f, fmaxf(-1.f, (tb - c) * hinv));
    }
    const float ua2 = ua + ua, ub2 = ub + ub;
    float fa1 = 0.f, fa2 = 0.f, fb1 = 0.f, fb2 = 0.f;
    #pragma unroll
    for (int m = NCHEB - 1; m >= 1; m--) {
        const float am = saF[m];
        float na = fmaf(ua2, fa1, am - fa2); fa2 = fa1; fa1 = na;
        float nb = fmaf(ub2, fb1, am - fb2); fb2 = fb1; fb1 = nb;
    }
    const float a0 = saF[0];
    const float Fa = fmaf(ua, fa1, a0 - fa2);
    const float Fb = fmaf(ub, fb1, a0 - fb2);

    {
        const float val = __fdividef(Fa, Z);
        const float sig = __fdividef(1.0f, 1.0f + ex2f(-val * L2E));
        g_act[b * S + i0] = sig * val * ps0 + __sinf(val) * ps1 + val * ps2;
    }
    {
        const float val = __fdividef(Fb, Z);
        const float sig = __fdividef(1.0f, 1.0f + ex2f(-val * L2E));
        g_act[b * S + i0 + 256] = sig * val * ps0 + __sinf(val) * ps1 + val * ps2;
    }
}

// ---------------- kernel 4: fc2 GEMM, grid (16 ctiles, 16 ksplit) ----------------
__global__ void __launch_bounds__(256) fc2_kernel(const float* __restrict__ W) {
    gemm_bf16<(S / FC2_KSPLIT) / 32>(g_act, W, g_fcp + (size_t)blockIdx.y * BS,
                                     blockIdx.x * 128, blockIdx.y * (S / FC2_KSPLIT));
}

// ---------------- kernel 5: combine fc2 partials + bias + LayerNorm ----------------
// grid BATCH, block 1024
__global__ void __launch_bounds__(1024) ln_kernel(const float* __restrict__ bias,
                                                  const float* __restrict__ g2,
                                                  const float* __restrict__ b2,
                                                  float* __restrict__ out) {
    __shared__ float sRow[S];
    __shared__ float rsum[32], rsq[32];
    __shared__ float sMu, sRstd;

    const int b = blockIdx.x;
    const int tid = threadIdx.x;
    const int lane = tid & 31, wid = tid >> 5;

    float s = 0.f, s2 = 0.f;
    #pragma unroll
    for (int it = 0; it < 2; it++) {
        int idx = tid + it * 1024;
        float v = bias[idx];
        #pragma unroll
        for (int p = 0; p < FC2_KSPLIT; p++)
            v += g_fcp[(size_t)p * BS + b * S + idx];
        sRow[idx] = v;
        s += v;
        s2 = fmaf(v, v, s2);
    }
    #pragma unroll
    for (int off = 16; off > 0; off >>= 1) {
        s  += __shfl_xor_sync(0xffffffffu, s,  off);
        s2 += __shfl_xor_sync(0xffffffffu, s2, off);
    }
    if (lane == 0) { rsum[wid] = s; rsq[wid] = s2; }
    __syncthreads();
    if (tid == 0) {
        float ts = 0.f, ts2 = 0.f;
        #pragma unroll
        for (int w = 0; w < 32; w++) { ts += rsum[w]; ts2 += rsq[w]; }
        float mu = ts * (1.0f / S);
        float var = ts2 * (1.0f / S) - mu * mu;
        sMu = mu;
        sRstd = rsqrtf(var + EPSLN);
    }
    __syncthreads();

    const float mu = sMu, rstd = sRstd;
    #pragma unroll
    for (int it = 0; it < 2; it++) {
        int idx = tid + it * 1024;
        out[b * S + idx] = (sRow[idx] - mu) * rstd * g2[idx] + b2[idx];
    }
}

// ---------------- launch ----------------
extern "C" void kernel_launch(void* const* d_in, const int* in_sizes, int n_in,
                              void* d_out, int out_size) {
    const float* x    = (const float*)d_in[0];
    const float* Wq   = (const float*)d_in[1];
    const float* Wk   = (const float*)d_in[2];
    const float* Wv   = (const float*)d_in[3];
    const float* p2   = (const float*)d_in[4];
    const float* Wfc2 = (const float*)d_in[5];
    const float* bfc2 = (const float*)d_in[6];
    const float* g2   = (const float*)d_in[7];
    const float* b2   = (const float*)d_in[8];
    float* out = (float*)d_out;

    qkv_kernel<<<dim3(16, QKV_KSPLIT, 3), 256>>>(x, Wq, Wk, Wv);
    combine_kernel<<<64, 256>>>();
    cheb_nodes_kernel<<<dim3(BATCH, 6), 256>>>();
    cheb_coef_kernel<<<BATCH, 256>>>();
    cheb_evalact_kernel<<<dim3(BATCH, 4), 256>>>(p2);
    fc2_kernel<<<dim3(16, FC2_KSPLIT), 256>>>(Wfc2);
    ln_kernel<<<BATCH, 1024>>>(bfc2, g2, b2, out);
}

// round 16
// speedup vs baseline: 1.0617x; 1.0617x over previous
#include <cuda_runtime.h>
#include <math.h>
#include <stdint.h>

#define BATCH 32
#define S 2048
#define BS (BATCH * S)
#define EPSLN 1e-5f
#define L2E 1.4426950408889634f   // log2(e)

#define QKV_KSPLIT 8
#define FC2_KSPLIT 16
#define NCHEB 32

// ---------------- scratch (no allocations allowed) ----------------
__device__ float g_qp[QKV_KSPLIT * BS];
__device__ float g_kp[QKV_KSPLIT * BS];
__device__ float g_vp[QKV_KSPLIT * BS];
__device__ float g_qc[BS];
__device__ float g_kc[BS];
__device__ float g_vc[BS];
__device__ float g_act[BS];
__device__ float g_fcp[FC2_KSPLIT * BS];
__device__ float g_F[BATCH * NCHEB];
__device__ float g_G[BATCH * NCHEB];
__device__ float g_S[BATCH * NCHEB];    // moments S_m = sum_i T_m(u_i)
__device__ float g_rqmn[64], g_rqmx[64], g_rkmn[64], g_rkmx[64];  // 1024-elem chunks

__device__ __forceinline__ float ex2f(float x) {
    float y;
    asm("ex2.approx.f32 %0, %1;" : "=f"(y) : "f"(x));
    return y;
}

__device__ __forceinline__ void cp_async16(unsigned dst, const void* src) {
    asm volatile("cp.async.cg.shared.global [%0], [%1], 16;" :: "r"(dst), "l"(src));
}

// split float2 (x = even-k, y = odd-k) into packed bf16x2 hi and lo planes.
__device__ __forceinline__ void bsplit(float2 v, uint32_t& hi, uint32_t& lo) {
    uint32_t h;
    asm("cvt.rn.bf16x2.f32 %0, %1, %2;" : "=r"(h) : "f"(v.y), "f"(v.x));
    float fx = __uint_as_float(h << 16);
    float fy = __uint_as_float(h & 0xffff0000u);
    float lx = v.x - fx, ly = v.y - fy;
    uint32_t l;
    asm("cvt.rn.bf16x2.f32 %0, %1, %2;" : "=r"(l) : "f"(ly), "f"(lx));
    hi = h; lo = l;
}

__device__ __forceinline__ void mma_bf16(float acc[4],
                                         uint32_t a0, uint32_t a1, uint32_t a2, uint32_t a3,
                                         uint32_t b0, uint32_t b1) {
    asm volatile("mma.sync.aligned.m16n8k16.row.col.f32.bf16.bf16.f32 "
                 "{%0,%1,%2,%3}, {%4,%5,%6,%7}, {%8,%9}, {%0,%1,%2,%3};"
                 : "+f"(acc[0]), "+f"(acc[1]), "+f"(acc[2]), "+f"(acc[3])
                 : "r"(a0), "r"(a1), "r"(a2), "r"(a3), "r"(b0), "r"(b1));
}

// warp-parallel DCT-II: lane m returns a_m = scale_m * sum_n src[n] cos(m theta_n),
// theta_n = pi (n+0.5)/NCHEB. cos via 3-term recurrence in n; src[n] by shuffle.
__device__ __forceinline__ float warp_dct(float srclane, int lane) {
    const float m = (float)lane;
    float cpp = cospif(0.5f * m * (1.0f / NCHEB));   // cos(m theta_0)
    float cp  = cospif(1.5f * m * (1.0f / NCHEB));   // cos(m theta_1)
    const float r = 2.0f * cospif(m * (1.0f / NCHEB));
    float s = __shfl_sync(0xffffffffu, srclane, 0) * cpp
            + __shfl_sync(0xffffffffu, srclane, 1) * cp;
    #pragma unroll
    for (int n = 2; n < NCHEB; n++) {
        float cn = fmaf(r, cp, -cpp);
        s = fmaf(__shfl_sync(0xffffffffu, srclane, n), cn, s);
        cpp = cp; cp = cn;
    }
    return s * ((lane == 0) ? (1.0f / NCHEB) : (2.0f / NCHEB));
}

// ---------------- bf16 tensor-core GEMM (unchanged from R12) ----------------
#define WSTRIDE 40
#define WSTAGE (128 * WSTRIDE)

template <int NCHUNK>
__device__ __forceinline__ void gemm_bf16(const float* __restrict__ X,
                                          const float* __restrict__ W,
                                          float* __restrict__ out,
                                          int c0, int kb0)
{
    __shared__ __align__(16) float sW[2][WSTAGE];
    __shared__ uint32_t sXh[512], sXl[512];

    const int tid = threadIdx.x;
    const int lane = tid & 31, w = tid >> 5;

    float acc[4][4];
    #pragma unroll
    for (int g = 0; g < 4; g++)
        #pragma unroll
        for (int j = 0; j < 4; j++) acc[g][j] = 0.f;

    const unsigned swbase = (unsigned)__cvta_generic_to_shared(&sW[0][0]);

    const int wrow = tid >> 3, wq = tid & 7;

    const int sg   = tid >> 6;
    const int sln  = (tid >> 1) & 31;
    const int sbrg = tid & 1;
    const int sn   = sg * 8 + (sln >> 2);
    const int skk  = sbrg * 8 + 2 * (sln & 3);
    const float* xp = X + (size_t)sn * S + kb0 + skk;

    #pragma unroll
    for (int i = 0; i < 4; i++) {
        int r = wrow + i * 32;
        cp_async16(swbase + (unsigned)((r * WSTRIDE + wq * 4) * 4),
                   W + (size_t)(c0 + r) * S + kb0 + wq * 4);
    }
    asm volatile("cp.async.commit_group;");
    float2 xr0 = *(const float2*)(xp);
    float2 xr1 = *(const float2*)(xp + 16);

    for (int ch = 0; ch < NCHUNK; ch++) {
        asm volatile("cp.async.wait_group 0;");
        __syncthreads();

        if (ch + 1 < NCHUNK) {
            const int kb = kb0 + (ch + 1) * 32;
            const unsigned stoff = (unsigned)(((ch + 1) & 1) * WSTAGE * 4);
            #pragma unroll
            for (int i = 0; i < 4; i++) {
                int r = wrow + i * 32;
                cp_async16(swbase + stoff + (unsigned)((r * WSTRIDE + wq * 4) * 4),
                           W + (size_t)(c0 + r) * S + kb + wq * 4);
            }
            asm volatile("cp.async.commit_group;");
        }

        {
            uint32_t h0, l0, h1, l1;
            bsplit(xr0, h0, l0);
            bsplit(xr1, h1, l1);
            sXh[tid] = h0;       sXl[tid] = l0;
            sXh[tid + 256] = h1; sXl[tid + 256] = l1;
        }
        if (ch + 1 < NCHUNK) {
            xr0 = *(const float2*)(xp + (ch + 1) * 32);
            xr1 = *(const float2*)(xp + (ch + 1) * 32 + 16);
        }
        __syncthreads();

        const float* ws = sW[ch & 1];
        const int rb = w * 16 + (lane >> 2);
        const int kc = 2 * (lane & 3);

        #pragma unroll
        for (int s = 0; s < 2; s++) {
            float2 ra0 = *(const float2*)&ws[rb * WSTRIDE + s * 16 + kc];
            float2 ra2 = *(const float2*)&ws[rb * WSTRIDE + s * 16 + 8 + kc];
            float2 ra1 = *(const float2*)&ws[(rb + 8) * WSTRIDE + s * 16 + kc];
            float2 ra3 = *(const float2*)&ws[(rb + 8) * WSTRIDE + s * 16 + 8 + kc];
            uint32_t A0h, A0l, A1h, A1l, A2h, A2l, A3h, A3l;
            bsplit(ra0, A0h, A0l);
            bsplit(ra1, A1h, A1l);
            bsplit(ra2, A2h, A2l);
            bsplit(ra3, A3h, A3l);

            #pragma unroll
            for (int g = 0; g < 4; g++) {
                const int base = ((s * 4 + g) << 6) + (lane << 1);
                uint2 bh = *(const uint2*)&sXh[base];
                uint2 bl = *(const uint2*)&sXl[base];
                mma_bf16(acc[g], A0h, A1h, A2h, A3h, bh.x, bh.y);
                mma_bf16(acc[g], A0h, A1h, A2h, A3h, bl.x, bl.y);
                mma_bf16(acc[g], A0l, A1l, A2l, A3l, bh.x, bh.y);
            }
        }
    }

    const int c = c0 + w * 16 + (lane >> 2);
    #pragma unroll
    for (int g = 0; g < 4; g++) {
        const int b = g * 8 + 2 * (lane & 3);
        out[(size_t)b * S + c]           = acc[g][0];
        out[(size_t)(b + 1) * S + c]     = acc[g][1];
        out[(size_t)b * S + c + 8]       = acc[g][2];
        out[(size_t)(b + 1) * S + c + 8] = acc[g][3];
    }
}

// ---------------- kernel 1: fused QKV GEMM ----------------
__global__ void __launch_bounds__(256) qkv_kernel(const float* __restrict__ x,
                                                  const float* __restrict__ Wq,
                                                  const float* __restrict__ Wk,
                                                  const float* __restrict__ Wv) {
    const int z = blockIdx.z;
    const float* W = (z == 0) ? Wq : (z == 1 ? Wk : Wv);
    float* out = ((z == 0) ? g_qp : (z == 1 ? g_kp : g_vp)) + (size_t)blockIdx.y * BS;
    gemm_bf16<(S / QKV_KSPLIT) / 32>(x, W, out, blockIdx.x * 128,
                                     blockIdx.y * (S / QKV_KSPLIT));
}

// ---------------- kernel 1b: combine qkv partials (float4) + 1024-chunk min/max ------
__global__ void __launch_bounds__(256) combine_kernel() {
    __shared__ float r0[8], r1[8], r2[8], r3[8];
    const int tid = threadIdx.x;
    const int e0 = (blockIdx.x * 256 + tid) * 4;

    float4 q = make_float4(0.f, 0.f, 0.f, 0.f);
    float4 k = q, v = q;
    #pragma unroll
    for (int p = 0; p < QKV_KSPLIT; p++) {
        float4 a = *(const float4*)&g_qp[(size_t)p * BS + e0];
        float4 bq = *(const float4*)&g_kp[(size_t)p * BS + e0];
        float4 c = *(const float4*)&g_vp[(size_t)p * BS + e0];
        q.x += a.x; q.y += a.y; q.z += a.z; q.w += a.w;
        k.x += bq.x; k.y += bq.y; k.z += bq.z; k.w += bq.w;
        v.x += c.x; v.y += c.y; v.z += c.z; v.w += c.w;
    }
    *(float4*)&g_qc[e0] = q;
    *(float4*)&g_kc[e0] = k;
    *(float4*)&g_vc[e0] = v;

    float qmn = fminf(fminf(q.x, q.y), fminf(q.z, q.w));
    float qmx = fmaxf(fmaxf(q.x, q.y), fmaxf(q.z, q.w));
    float kmn = fminf(fminf(k.x, k.y), fminf(k.z, k.w));
    float kmx = fmaxf(fmaxf(k.x, k.y), fmaxf(k.z, k.w));
    #pragma unroll
    for (int off = 16; off > 0; off >>= 1) {
        qmn = fminf(qmn, __shfl_xor_sync(0xffffffffu, qmn, off));
        qmx = fmaxf(qmx, __shfl_xor_sync(0xffffffffu, qmx, off));
        kmn = fminf(kmn, __shfl_xor_sync(0xffffffffu, kmn, off));
        kmx = fmaxf(kmx, __shfl_xor_sync(0xffffffffu, kmx, off));
    }
    const int lane = tid & 31, wid = tid >> 5;
    if (lane == 0) { r0[wid] = qmn; r1[wid] = qmx; r2[wid] = kmn; r3[wid] = kmx; }
    __syncthreads();
    if (tid == 0) {
        float a = r0[0], b = r1[0], c = r2[0], d = r3[0];
        #pragma unroll
        for (int w = 1; w < 8; w++) {
            a = fminf(a, r0[w]); b = fmaxf(b, r1[w]);
            c = fminf(c, r2[w]); d = fmaxf(d, r3[w]);
        }
        g_rqmn[blockIdx.x] = a; g_rqmx[blockIdx.x] = b;
        g_rkmn[blockIdx.x] = c; g_rkmx[blockIdx.x] = d;
    }
}

// batch-level range + shift M (identical fp sequence wherever used; 2 chunks/batch)
__device__ __forceinline__ void batch_range(int b, float& c, float& h, float& M) {
    float qmn = fminf(g_rqmn[b * 2], g_rqmn[b * 2 + 1]);
    float qmx = fmaxf(g_rqmx[b * 2], g_rqmx[b * 2 + 1]);
    float kmn = fminf(g_rkmn[b * 2], g_rkmn[b * 2 + 1]);
    float kmx = fmaxf(g_rkmx[b * 2], g_rkmx[b * 2 + 1]);
    c = 0.5f * (qmn + qmx);
    h = fmaxf(0.5f * (qmx - qmn), 1e-30f);
    M = fmaxf(fmaxf(qmn * kmn, qmn * kmx), fmaxf(qmx * kmn, qmx * kmx));
}

// ---------------- kernel 2a: Chebyshev nodes (y<4) + q-moments (y==4) ----------------
__global__ void __launch_bounds__(256) cheb_nodes_kernel() {
    __shared__ float sk[S], sv[S];
    __shared__ float sprm[3];
    __shared__ float sS[NCHEB][9];

    const int b = blockIdx.x;
    const int tid = threadIdx.x;
    const int lane = tid & 31, w = tid >> 5;

    if (tid == 0) {
        float c, h, M;
        batch_range(b, c, h, M);
        sprm[0] = c; sprm[1] = h; sprm[2] = M;
    }

    if (blockIdx.y == 4) {
        // ---- moments path ----
        __syncthreads();
        const float c = sprm[0], hinv = 1.0f / sprm[1];

        float acc[NCHEB];
        #pragma unroll
        for (int m = 0; m < NCHEB; m++) acc[m] = 0.f;

        #pragma unroll
        for (int jj = 0; jj < 8; jj++) {
            const int i = tid + jj * 256;
            float u = fminf(1.f, fmaxf(-1.f, (g_qc[b * S + i] - c) * hinv));
            float t0 = 1.f, t1 = u;
            acc[0] += t0;
            acc[1] += t1;
            #pragma unroll
            for (int m = 2; m < NCHEB; m++) {
                float tm = fmaf(u + u, t1, -t0);
                acc[m] += tm;
                t0 = t1; t1 = tm;
            }
        }
        #pragma unroll
        for (int m = 0; m < NCHEB; m++) {
            float s = acc[m];
            #pragma unroll
            for (int off = 16; off > 0; off >>= 1)
                s += __shfl_xor_sync(0xffffffffu, s, off);
            if (lane == 0) sS[m][w] = s;
        }
        __syncthreads();
        if (tid < NCHEB) {
            float s = 0.f;
            #pragma unroll
            for (int ww = 0; ww < 8; ww++) s += sS[tid][ww];
            g_S[b * NCHEB + tid] = s;
        }
        return;
    }

    // ---- nodes path: 8 nodes per block, 1 per warp ----
    for (int idx = tid; idx < S; idx += 256) {
        sk[idx] = g_kc[b * S + idx];
        sv[idx] = g_vc[b * S + idx];
    }
    __syncthreads();
    const float c = sprm[0], h = sprm[1], Ml2e = sprm[2] * L2E;

    const int n = blockIdx.y * 8 + w;
    const float t = fmaf(h, cospif((n + 0.5f) * (1.0f / NCHEB)), c);
    const float tl = t * L2E;
    float F = 0.f, G = 0.f;
    #pragma unroll 4
    for (int j = lane; j < S; j += 32) {
        float e = ex2f(fmaf(tl, sk[j], -Ml2e));
        F = fmaf(e, sv[j], F);
        G += e;
    }
    #pragma unroll
    for (int off = 16; off > 0; off >>= 1) {
        F += __shfl_xor_sync(0xffffffffu, F, off);
        G += __shfl_xor_sync(0xffffffffu, G, off);
    }
    if (lane == 0) {
        g_F[b * NCHEB + n] = F;
        g_G[b * NCHEB + n] = G;
    }
}

// ---------------- kernel 2b: inline warp-DCT + Z + Clenshaw + activation --------------
// grid (BATCH, 4), block 256, 2 i per thread. Warp 0: F-DCT; warp 1: G-DCT + Z.
__global__ void __launch_bounds__(256) cheb_evalact_kernel(const float* __restrict__ p2) {
    __shared__ float saF[NCHEB];
    __shared__ float sprm[2];
    __shared__ float sZ, sPs0, sPs1, sPs2;

    const int b = blockIdx.x;
    const int tid = threadIdx.x;
    const int lane = tid & 31, wid = tid >> 5;

    if (tid == 64) {
        float c, h, M;
        batch_range(b, c, h, M);
        sprm[0] = c; sprm[1] = h;
    }
    if (tid == 96) {
        float p[5];
        #pragma unroll
        for (int t = 0; t < 5; t++) p[t] = p2[t];
        float pm = p[0];
        #pragma unroll
        for (int t = 1; t < 5; t++) pm = fmaxf(pm, p[t]);
        float pe[5], psum = 0.f;
        #pragma unroll
        for (int t = 0; t < 5; t++) { pe[t] = ex2f((p[t] - pm) * L2E); psum += pe[t]; }
        float inv = __fdividef(1.0f, psum);
        sPs0 = pe[0] * inv; sPs1 = pe[1] * inv; sPs2 = pe[2] * inv;
    }
    if (wid == 0) {
        // F coefficients
        float src = g_F[b * NCHEB + lane];
        saF[lane] = warp_dct(src, lane);
    } else if (wid == 1) {
        // G coefficients -> Z = sum_m a^G_m S_m
        float src = g_G[b * NCHEB + lane];
        float ag = warp_dct(src, lane);
        float z = ag * g_S[b * NCHEB + lane];
        #pragma unroll
        for (int off = 16; off > 0; off >>= 1)
            z += __shfl_xor_sync(0xffffffffu, z, off);
        if (lane == 0) sZ = z;
    }
    __syncthreads();

    const float c = sprm[0], hinv = 1.0f / sprm[1];
    const float Z = sZ;
    const float ps0 = sPs0, ps1 = sPs1, ps2 = sPs2;

    const int i0 = blockIdx.y * 512 + tid;
    float ua, ub;
    {
        float ta = g_qc[b * S + i0];
        float tb = g_qc[b * S + i0 + 256];
        ua = fminf(1.f, fmaxf(-1.f, (ta - c) * hinv));
        ub = fminf(1.f, fmaxf(-1.f, (tb - c) * hinv));
    }
    const float ua2 = ua + ua, ub2 = ub + ub;
    float fa1 = 0.f, fa2 = 0.f, fb1 = 0.f, fb2 = 0.f;
    #pragma unroll
    for (int m = NCHEB - 1; m >= 1; m--) {
        const float am = saF[m];
        float na = fmaf(ua2, fa1, am - fa2); fa2 = fa1; fa1 = na;
        float nb = fmaf(ub2, fb1, am - fb2); fb2 = fb1; fb1 = nb;
    }
    const float a0 = saF[0];
    const float Fa = fmaf(ua, fa1, a0 - fa2);
    const float Fb = fmaf(ub, fb1, a0 - fb2);

    {
        const float val = __fdividef(Fa, Z);
        const float sig = __fdividef(1.0f, 1.0f + ex2f(-val * L2E));
        g_act[b * S + i0] = sig * val * ps0 + __sinf(val) * ps1 + val * ps2;
    }
    {
        const float val = __fdividef(Fb, Z);
        const float sig = __fdividef(1.0f, 1.0f + ex2f(-val * L2E));
        g_act[b * S + i0 + 256] = sig * val * ps0 + __sinf(val) * ps1 + val * ps2;
    }
}

// ---------------- kernel 4: fc2 GEMM, grid (16 ctiles, 16 ksplit) ----------------
__global__ void __launch_bounds__(256) fc2_kernel(const float* __restrict__ W) {
    gemm_bf16<(S / FC2_KSPLIT) / 32>(g_act, W, g_fcp + (size_t)blockIdx.y * BS,
                                     blockIdx.x * 128, blockIdx.y * (S / FC2_KSPLIT));
}

// ---------------- kernel 5: combine fc2 partials + bias + LayerNorm ----------------
__global__ void __launch_bounds__(1024) ln_kernel(const float* __restrict__ bias,
                                                  const float* __restrict__ g2,
                                                  const float* __restrict__ b2,
                                                  float* __restrict__ out) {
    __shared__ float sRow[S];
    __shared__ float rsum[32], rsq[32];
    __shared__ float sMu, sRstd;

    const int b = blockIdx.x;
    const int tid = threadIdx.x;
    const int lane = tid & 31, wid = tid >> 5;

    float s = 0.f, s2 = 0.f;
    #pragma unroll
    for (int it = 0; it < 2; it++) {
        int idx = tid + it * 1024;
        float v = bias[idx];
        #pragma unroll
        for (int p = 0; p < FC2_KSPLIT; p++)
            v += g_fcp[(size_t)p * BS + b * S + idx];
        sRow[idx] = v;
        s += v;
        s2 = fmaf(v, v, s2);
    }
    #pragma unroll
    for (int off = 16; off > 0; off >>= 1) {
        s  += __shfl_xor_sync(0xffffffffu, s,  off);
        s2 += __shfl_xor_sync(0xffffffffu, s2, off);
    }
    if (lane == 0) { rsum[wid] = s; rsq[wid] = s2; }
    __syncthreads();
    if (tid == 0) {
        float ts = 0.f, ts2 = 0.f;
        #pragma unroll
        for (int w = 0; w < 32; w++) { ts += rsum[w]; ts2 += rsq[w]; }
        float mu = ts * (1.0f / S);
        float var = ts2 * (1.0f / S) - mu * mu;
        sMu = mu;
        sRstd = rsqrtf(var + EPSLN);
    }
    __syncthreads();

    const float mu = sMu, rstd = sRstd;
    #pragma unroll
    for (int it = 0; it < 2; it++) {
        int idx = tid + it * 1024;
        out[b * S + idx] = (sRow[idx] - mu) * rstd * g2[idx] + b2[idx];
    }
}

// ---------------- launch ----------------
extern "C" void kernel_launch(void* const* d_in, const int* in_sizes, int n_in,
                              void* d_out, int out_size) {
    const float* x    = (const float*)d_in[0];
    const float* Wq   = (const float*)d_in[1];
    const float* Wk   = (const float*)d_in[2];
    const float* Wv   = (const float*)d_in[3];
    const float* p2   = (const float*)d_in[4];
    const float* Wfc2 = (const float*)d_in[5];
    const float* bfc2 = (const float*)d_in[6];
    const float* g2   = (const float*)d_in[7];
    const float* b2   = (const float*)d_in[8];
    float* out = (float*)d_out;

    qkv_kernel<<<dim3(16, QKV_KSPLIT, 3), 256>>>(x, Wq, Wk, Wv);
    combine_kernel<<<64, 256>>>();
    cheb_nodes_kernel<<<dim3(BATCH, 5), 256>>>();
    cheb_evalact_kernel<<<dim3(BATCH, 4), 256>>>(p2);
    fc2_kernel<<<dim3(16, FC2_KSPLIT), 256>>>(Wfc2);
    ln_kernel<<<BATCH, 1024>>>(bfc2, g2, b2, out);
}